// round 8
// baseline (speedup 1.0000x reference)
#include <cuda_runtime.h>
#include <cuda_bf16.h>
#include <cstdint>

#define TV 16384
#define V_SZ 1024
#define T_SZ 16
#define B_SZ 256
#define JT 8              // W rows per CTA
#define THREADS 256       // one thread per batch element
#define QF 4096           // floats per quarter-row (4 t-slots)
#define QBYTES (QF * 4)   // 16 KB
#define NBUF 3            // triple buffer
#define NQ (JT * 4)       // quarters per CTA

template<int N> __device__ __forceinline__ void cp_wait() {
    asm volatile("cp.async.wait_group %0;\n" :: "n"(N) : "memory");
}
__device__ __forceinline__ void cp_commit() {
    asm volatile("cp.async.commit_group;\n" ::: "memory");
}

// ---------------------------------------------------------------------------
// Per CTA: JT=8 consecutive W rows x all 256 batches (thread = batch).
// Rows streamed densely as 16KB quarters via per-thread cp.async.cg
// (4 chunks/thread/quarter, purely affine addressing), triple buffered:
// while gathering quarter k, quarter k+1 streams; k+2 issued after gather.
// Gather index within a quarter is just x[b][t] + (t&3)*1024 (dense layout).
// ---------------------------------------------------------------------------
__global__ void __launch_bounds__(THREADS, 4) gather_sum_relu_kernel(
    const void* __restrict__ x_raw,     // [B, T] int64 or int32
    const float* __restrict__ W,        // [TV, TV] row-major
    const float* __restrict__ bias,     // [TV]
    float* __restrict__ out)            // [B, TV]
{
    extern __shared__ float buf[];                   // NBUF * QF floats
    const int tid = threadIdx.x;                     // = batch b
    const int j0 = blockIdx.x * JT;
    const uint32_t buf_sa = (uint32_t)__cvta_generic_to_shared(buf);

    // ---- gather indices (dtype-robust: int64 values in [0,V) look like (v,0)) ----
    const long long* x64 = (const long long*)x_raw;
    const int*       x32 = (const int*)x_raw;
    long long v64[T_SZ];
    bool ok64 = true;
    #pragma unroll
    for (int t = 0; t < T_SZ; t++) {
        v64[t] = x64[tid * T_SZ + t];
        if (v64[t] < 0 || v64[t] >= V_SZ) ok64 = false;
    }
    int c[T_SZ];   // float offset within the quarter that owns t-slot t
    #pragma unroll
    for (int t = 0; t < T_SZ; t++) {
        int xi = ok64 ? (int)v64[t] : x32[tid * T_SZ + t];
        c[t] = xi + (t & 3) * V_SZ;                  // t-slot t lives in quarter t>>2
    }

    // Issue quarter q (row q>>2, quarter-in-row q&3) into buffer q%NBUF.
    auto issue = [&](int q) {
        const float* src = W + (size_t)(j0 + (q >> 2)) * TV + (q & 3) * QF;
        const uint32_t dbase = buf_sa + (q % NBUF) * QBYTES;
        #pragma unroll
        for (int j = 0; j < QF / 4 / THREADS; j++) { // 4 chunks of 16B per thread
            const int i = tid + j * THREADS;         // chunk id 0..1023
            asm volatile("cp.async.cg.shared.global [%0], [%1], 16;\n"
                         :: "r"(dbase + i * 16), "l"(src + i * 4));
        }
        cp_commit();
    };

    issue(0);
    issue(1);

    float acc[JT];
    for (int k = 0; k < NQ; k++) {
        if (k == NQ - 1) cp_wait<0>(); else cp_wait<1>();
        __syncthreads();                             // all threads' chunks visible

        const float* b = buf + (k % NBUF) * QF;
        const int q = k & 3;                         // quarter-in-row
        float s;
        if      (q == 0) s = b[c[0]]  + b[c[1]]  + b[c[2]]  + b[c[3]];
        else if (q == 1) s = b[c[4]]  + b[c[5]]  + b[c[6]]  + b[c[7]];
        else if (q == 2) s = b[c[8]]  + b[c[9]]  + b[c[10]] + b[c[11]];
        else             s = b[c[12]] + b[c[13]] + b[c[14]] + b[c[15]];

        const int row = k >> 2;
        acc[row] = (q == 0) ? s : (acc[row] + s);

        __syncthreads();                             // buffer free before re-issue
        if (k + 2 < NQ) issue(k + 2);
    }

    // ---- bias + relu + 32B contiguous store per thread (one DRAM sector) ----
    float r[JT];
    #pragma unroll
    for (int jj = 0; jj < JT; jj++) {
        float v = acc[jj] + bias[j0 + jj];
        r[jj] = v > 0.f ? v : 0.f;
    }
    float4* o = (float4*)(out + (size_t)tid * TV + j0);
    o[0] = make_float4(r[0], r[1], r[2], r[3]);
    o[1] = make_float4(r[4], r[5], r[6], r[7]);
}

extern "C" void kernel_launch(void* const* d_in, const int* in_sizes, int n_in,
                              void* d_out, int out_size) {
    const void*  x    = d_in[0];                 // [256, 16] int64/int32
    const float* W    = (const float*)d_in[1];   // [16384, 16384]
    const float* bias = (const float*)d_in[2];   // [16384]
    float* out = (float*)d_out;                  // [256, 16384]

    const int smem_bytes = NBUF * QBYTES;        // 48 KB -> 4 CTAs/SM
    static bool attr_set = false;
    if (!attr_set) {
        cudaFuncSetAttribute(gather_sum_relu_kernel,
                             cudaFuncAttributeMaxDynamicSharedMemorySize, smem_bytes);
        attr_set = true;
    }

    gather_sum_relu_kernel<<<TV / JT, THREADS, smem_bytes>>>(x, W, bias, out);
}

// round 10
// speedup vs baseline: 1.0449x; 1.0449x over previous
#include <cuda_runtime.h>
#include <cuda_bf16.h>
#include <cstdint>

#define TV 16384
#define V_SZ 1024
#define T_SZ 16
#define B_SZ 256
#define JT 8              // W rows per CTA
#define THREADS 256       // one thread per batch element
#define QF 4096           // floats per quarter-row (4 t-slots)
#define QBYTES (QF * 4)   // 16 KB
#define NBUF 4            // quad buffer -> 2 groups (32KB) in flight during gather
#define NQ (JT * 4)       // quarters per CTA

template<int N> __device__ __forceinline__ void cp_wait() {
    asm volatile("cp.async.wait_group %0;\n" :: "n"(N) : "memory");
}
__device__ __forceinline__ void cp_commit() {
    asm volatile("cp.async.commit_group;\n" ::: "memory");
}

// ---------------------------------------------------------------------------
// Per CTA: JT=8 consecutive W rows x all 256 batches (thread = batch).
// Rows streamed densely as 16KB quarters via per-thread cp.async.cg with
// purely affine addressing. 4-deep buffering, wait_group<2>: while gathering
// quarter k, quarters k+1 and k+2 (32KB) are streaming from DRAM; quarter
// k+3 is issued right after the gather. Single barrier per iteration: the
// top-of-iteration sync already orders all threads past the k-1 gather that
// used the buffer k+3 overwrites.
// ---------------------------------------------------------------------------
__global__ void __launch_bounds__(THREADS, 3) gather_sum_relu_kernel(
    const void* __restrict__ x_raw,     // [B, T] int64 or int32
    const float* __restrict__ W,        // [TV, TV] row-major
    const float* __restrict__ bias,     // [TV]
    float* __restrict__ out)            // [B, TV]
{
    extern __shared__ float buf[];                   // NBUF * QF floats
    const int tid = threadIdx.x;                     // = batch b
    const int j0 = blockIdx.x * JT;
    const uint32_t buf_sa = (uint32_t)__cvta_generic_to_shared(buf);

    // ---- gather indices (dtype-robust: int64 values in [0,V) look like (v,0)) ----
    const long long* x64 = (const long long*)x_raw;
    const int*       x32 = (const int*)x_raw;
    long long v64[T_SZ];
    bool ok64 = true;
    #pragma unroll
    for (int t = 0; t < T_SZ; t++) {
        v64[t] = x64[tid * T_SZ + t];
        if (v64[t] < 0 || v64[t] >= V_SZ) ok64 = false;
    }
    int c[T_SZ];   // float offset within the quarter that owns t-slot t
    #pragma unroll
    for (int t = 0; t < T_SZ; t++) {
        int xi = ok64 ? (int)v64[t] : x32[tid * T_SZ + t];
        c[t] = xi + (t & 3) * V_SZ;                  // t-slot t lives in quarter t>>2
    }

    // Issue quarter q (row q>>2, quarter-in-row q&3) into buffer q%NBUF.
    auto issue = [&](int q) {
        const float* src = W + (size_t)(j0 + (q >> 2)) * TV + (q & 3) * QF;
        const uint32_t dbase = buf_sa + (q % NBUF) * QBYTES;
        #pragma unroll
        for (int j = 0; j < QF / 4 / THREADS; j++) { // 4 chunks of 16B per thread
            const int i = tid + j * THREADS;         // chunk id 0..1023
            asm volatile("cp.async.cg.shared.global [%0], [%1], 16;\n"
                         :: "r"(dbase + i * 16), "l"(src + i * 4));
        }
        cp_commit();
    };

    issue(0);
    issue(1);
    issue(2);

    float acc[JT];
    for (int k = 0; k < NQ; k++) {
        // Ensure group k is complete; keep up to 2 later groups in flight.
        if (k <= NQ - 3)      cp_wait<2>();
        else if (k == NQ - 2) cp_wait<1>();
        else                  cp_wait<0>();
        __syncthreads();                             // all threads' chunks visible
                                                     // (also frees buf[(k+3)%4])
        const float* b = buf + (k % NBUF) * QF;
        const int q = k & 3;                         // quarter-in-row
        float s;
        if      (q == 0) s = b[c[0]]  + b[c[1]]  + b[c[2]]  + b[c[3]];
        else if (q == 1) s = b[c[4]]  + b[c[5]]  + b[c[6]]  + b[c[7]];
        else if (q == 2) s = b[c[8]]  + b[c[9]]  + b[c[10]] + b[c[11]];
        else             s = b[c[12]] + b[c[13]] + b[c[14]] + b[c[15]];

        const int row = k >> 2;
        acc[row] = (q == 0) ? s : (acc[row] + s);

        if (k + 3 < NQ) issue(k + 3);
    }

    // ---- bias + relu + 32B contiguous store per thread (one DRAM sector) ----
    float r[JT];
    #pragma unroll
    for (int jj = 0; jj < JT; jj++) {
        float v = acc[jj] + bias[j0 + jj];
        r[jj] = v > 0.f ? v : 0.f;
    }
    float4* o = (float4*)(out + (size_t)tid * TV + j0);
    o[0] = make_float4(r[0], r[1], r[2], r[3]);
    o[1] = make_float4(r[4], r[5], r[6], r[7]);
}

extern "C" void kernel_launch(void* const* d_in, const int* in_sizes, int n_in,
                              void* d_out, int out_size) {
    const void*  x    = d_in[0];                 // [256, 16] int64/int32
    const float* W    = (const float*)d_in[1];   // [16384, 16384]
    const float* bias = (const float*)d_in[2];   // [16384]
    float* out = (float*)d_out;                  // [256, 16384]

    const int smem_bytes = NBUF * QBYTES;        // 64 KB -> 3 CTAs/SM
    static bool attr_set = false;
    if (!attr_set) {
        cudaFuncSetAttribute(gather_sum_relu_kernel,
                             cudaFuncAttributeMaxDynamicSharedMemorySize, smem_bytes);
        attr_set = true;
    }

    gather_sum_relu_kernel<<<TV / JT, THREADS, smem_bytes>>>(x, W, bias, out);
}

// round 11
// speedup vs baseline: 1.0664x; 1.0205x over previous
#include <cuda_runtime.h>
#include <cuda_bf16.h>
#include <cstdint>

#define TV 16384
#define V_SZ 1024
#define T_SZ 16
#define B_SZ 256
#define JT 8              // W rows per CTA
#define THREADS 256       // one thread per batch element
#define QF 4096           // floats per quarter-row (4 t-slots)
#define QBYTES (QF * 4)   // 16 KB
#define NBUF 4            // 4 buffers; issue-ahead=4 -> 3 groups (48KB) in flight
#define NQ (JT * 4)       // quarters per CTA

template<int N> __device__ __forceinline__ void cp_wait() {
    asm volatile("cp.async.wait_group %0;\n" :: "n"(N) : "memory");
}
__device__ __forceinline__ void cp_commit() {
    asm volatile("cp.async.commit_group;\n" ::: "memory");
}

// ---------------------------------------------------------------------------
// Per CTA: JT=8 consecutive W rows x all 256 batches (thread = batch).
// Dense 16KB quarters via per-thread cp.async.cg, 4-deep ring with
// issue-ahead of 4: while gathering quarter k, quarters k+1..k+3 (48KB)
// are streaming from DRAM (144KB in flight per SM at 3 CTAs/SM). The
// post-gather __syncthreads frees buffer k%4 so issue(k+4) can target it.
// ---------------------------------------------------------------------------
__global__ void __launch_bounds__(THREADS, 3) gather_sum_relu_kernel(
    const void* __restrict__ x_raw,     // [B, T] int64 or int32
    const float* __restrict__ W,        // [TV, TV] row-major
    const float* __restrict__ bias,     // [TV]
    float* __restrict__ out)            // [B, TV]
{
    extern __shared__ float buf[];                   // NBUF * QF floats
    const int tid = threadIdx.x;                     // = batch b
    const int j0 = blockIdx.x * JT;
    const uint32_t buf_sa = (uint32_t)__cvta_generic_to_shared(buf);

    // ---- gather indices (dtype-robust: int64 values in [0,V) look like (v,0)) ----
    const long long* x64 = (const long long*)x_raw;
    const int*       x32 = (const int*)x_raw;
    long long v64[T_SZ];
    bool ok64 = true;
    #pragma unroll
    for (int t = 0; t < T_SZ; t++) {
        v64[t] = x64[tid * T_SZ + t];
        if (v64[t] < 0 || v64[t] >= V_SZ) ok64 = false;
    }
    int c[T_SZ];   // float offset within the quarter that owns t-slot t
    #pragma unroll
    for (int t = 0; t < T_SZ; t++) {
        int xi = ok64 ? (int)v64[t] : x32[tid * T_SZ + t];
        c[t] = xi + (t & 3) * V_SZ;                  // t-slot t lives in quarter t>>2
    }

    // Issue quarter q (row q>>2, quarter-in-row q&3) into buffer q%NBUF.
    auto issue = [&](int q) {
        const float* src = W + (size_t)(j0 + (q >> 2)) * TV + (q & 3) * QF;
        const uint32_t dbase = buf_sa + (q % NBUF) * QBYTES;
        #pragma unroll
        for (int j = 0; j < QF / 4 / THREADS; j++) { // 4 chunks of 16B per thread
            const int i = tid + j * THREADS;         // chunk id 0..1023
            asm volatile("cp.async.cg.shared.global [%0], [%1], 16;\n"
                         :: "r"(dbase + i * 16), "l"(src + i * 4));
        }
        cp_commit();
    };

    issue(0); issue(1); issue(2); issue(3);

    float acc[JT];
    for (int k = 0; k < NQ; k++) {
        // Group k must be complete; keep the rest (up to 3 = 48KB) in flight.
        const int rem = NQ - 1 - k;                  // groups younger than k
        if (rem >= 3)      cp_wait<3>();
        else if (rem == 2) cp_wait<2>();
        else if (rem == 1) cp_wait<1>();
        else               cp_wait<0>();
        __syncthreads();                             // group k visible to all

        const float* b = buf + (k % NBUF) * QF;
        const int q = k & 3;                         // quarter-in-row
        float s;
        if      (q == 0) s = b[c[0]]  + b[c[1]]  + b[c[2]]  + b[c[3]];
        else if (q == 1) s = b[c[4]]  + b[c[5]]  + b[c[6]]  + b[c[7]];
        else if (q == 2) s = b[c[8]]  + b[c[9]]  + b[c[10]] + b[c[11]];
        else             s = b[c[12]] + b[c[13]] + b[c[14]] + b[c[15]];

        const int row = k >> 2;
        acc[row] = (q == 0) ? s : (acc[row] + s);

        __syncthreads();                             // buffer k%4 free for reuse
        if (k + NBUF < NQ) issue(k + NBUF);
    }

    // ---- bias + relu + 32B contiguous store per thread (one DRAM sector) ----
    float r[JT];
    #pragma unroll
    for (int jj = 0; jj < JT; jj++) {
        float v = acc[jj] + bias[j0 + jj];
        r[jj] = v > 0.f ? v : 0.f;
    }
    float4* o = (float4*)(out + (size_t)tid * TV + j0);
    o[0] = make_float4(r[0], r[1], r[2], r[3]);
    o[1] = make_float4(r[4], r[5], r[6], r[7]);
}

extern "C" void kernel_launch(void* const* d_in, const int* in_sizes, int n_in,
                              void* d_out, int out_size) {
    const void*  x    = d_in[0];                 // [256, 16] int64/int32
    const float* W    = (const float*)d_in[1];   // [16384, 16384]
    const float* bias = (const float*)d_in[2];   // [16384]
    float* out = (float*)d_out;                  // [256, 16384]

    const int smem_bytes = NBUF * QBYTES;        // 64 KB -> 3 CTAs/SM
    static bool attr_set = false;
    if (!attr_set) {
        cudaFuncSetAttribute(gather_sum_relu_kernel,
                             cudaFuncAttributeMaxDynamicSharedMemorySize, smem_bytes);
        attr_set = true;
    }

    gather_sum_relu_kernel<<<TV / JT, THREADS, smem_bytes>>>(x, W, bias, out);
}

// round 12
// speedup vs baseline: 1.1794x; 1.1059x over previous
#include <cuda_runtime.h>
#include <cuda_bf16.h>
#include <cstdint>

#define TV 16384
#define V_SZ 1024
#define T_SZ 16
#define B_SZ 256
#define JT 8                // W rows per CTA
#define NCONS 256           // consumer threads (one per batch element)
#define NTHREADS 288        // + 1 producer warp
#define QF 4096             // floats per quarter-row (4 t-slots)
#define QBYTES (QF * 4)     // 16 KB
#define NBUF 4              // ring stages (stage == quarter-in-row)
#define NQ (JT * 4)         // quarters per CTA

__device__ __forceinline__ void mbar_wait(uint32_t mbar, int parity) {
    asm volatile(
        "{\n\t"
        ".reg .pred P;\n\t"
        "WL_%=:\n\t"
        "mbarrier.try_wait.parity.acquire.cta.shared::cta.b64 P, [%0], %1, 0x989680;\n\t"
        "@P bra.uni WD_%=;\n\t"
        "bra.uni WL_%=;\n\t"
        "WD_%=:\n\t"
        "}" :: "r"(mbar), "r"(parity) : "memory");
}

// ---------------------------------------------------------------------------
// Warp-specialized streaming: producer warp issues dense 16KB cp.async.bulk
// transfers through a 4-stage mbarrier ring (waits only on per-stage empty
// barriers -> re-issues the moment a buffer frees). Consumer warps (thread =
// batch) wait on full barriers, gather 4 elements, and arrive empty via one
// lane per warp. No CTA-wide barrier anywhere in the loop.
// ---------------------------------------------------------------------------
__global__ void __launch_bounds__(NTHREADS, 3) gather_sum_relu_kernel(
    const void* __restrict__ x_raw,     // [B, T] int64 or int32
    const float* __restrict__ W,        // [TV, TV] row-major
    const float* __restrict__ bias,     // [TV]
    float* __restrict__ out)            // [B, TV]
{
    extern __shared__ float buf[];                    // NBUF * QF floats
    __shared__ __align__(8) unsigned long long mb_full[NBUF];
    __shared__ __align__(8) unsigned long long mb_empty[NBUF];

    const int tid = threadIdx.x;
    const int j0 = blockIdx.x * JT;
    const uint32_t buf_sa   = (uint32_t)__cvta_generic_to_shared(buf);
    const uint32_t full_sa  = (uint32_t)__cvta_generic_to_shared(mb_full);
    const uint32_t empty_sa = (uint32_t)__cvta_generic_to_shared(mb_empty);

    if (tid == 0) {
        #pragma unroll
        for (int i = 0; i < NBUF; i++) {
            asm volatile("mbarrier.init.shared.b64 [%0], 1;"
                         :: "r"(full_sa + i * 8) : "memory");   // producer arrive+tx
            asm volatile("mbarrier.init.shared.b64 [%0], 8;"
                         :: "r"(empty_sa + i * 8) : "memory");  // 8 consumer warps
        }
    }
    __syncthreads();                                  // barriers visible to all

    if (tid >= NCONS) {
        // ---------------- producer warp (lane 0 only) ----------------
        if (tid == NCONS) {
            for (int q = 0; q < NQ; q++) {
                const int st = q & 3;                 // stage == quarter-in-row
                const int ph = ((q >> 2) & 1) ^ 1;    // starts 1: fresh-barrier pass
                mbar_wait(empty_sa + st * 8, ph);
                const uint32_t mb = full_sa + st * 8;
                asm volatile("mbarrier.arrive.expect_tx.shared.b64 _, [%0], %1;"
                             :: "r"(mb), "r"(QBYTES) : "memory");
                const float* src = W + (size_t)(j0 + (q >> 2)) * TV + st * QF;
                asm volatile(
                    "cp.async.bulk.shared::cta.global.mbarrier::complete_tx::bytes "
                    "[%0], [%1], %2, [%3];"
                    :: "r"(buf_sa + st * QBYTES), "l"(src), "r"(QBYTES), "r"(mb)
                    : "memory");
            }
        }
        return;
    }

    // ---------------- consumer threads (thread = batch) ----------------
    // Gather indices (dtype-robust: int64 values in [0,V) look like (v,0)).
    const long long* x64 = (const long long*)x_raw;
    const int*       x32 = (const int*)x_raw;
    long long v64[T_SZ];
    bool ok64 = true;
    #pragma unroll
    for (int t = 0; t < T_SZ; t++) {
        v64[t] = x64[tid * T_SZ + t];
        if (v64[t] < 0 || v64[t] >= V_SZ) ok64 = false;
    }
    int c[T_SZ];   // float offset within the quarter that owns t-slot t
    #pragma unroll
    for (int t = 0; t < T_SZ; t++) {
        int xi = ok64 ? (int)v64[t] : x32[tid * T_SZ + t];
        c[t] = xi + (t & 3) * V_SZ;
    }

    const int lane = tid & 31;
    float acc[JT];

    for (int r = 0; r < JT; r++) {
        float s = 0.f;
        #pragma unroll
        for (int q = 0; q < 4; q++) {
            mbar_wait(full_sa + q * 8, r & 1);
            const float* b = buf + q * QF;
            s += b[c[q * 4 + 0]] + b[c[q * 4 + 1]]
               + b[c[q * 4 + 2]] + b[c[q * 4 + 3]];
            __syncwarp();
            if (lane == 0)
                asm volatile("mbarrier.arrive.shared.b64 _, [%0];"
                             :: "r"(empty_sa + q * 8) : "memory");
        }
        acc[r] = s;
    }

    // bias + relu + 32B contiguous store per thread (one DRAM sector)
    float rr[JT];
    #pragma unroll
    for (int jj = 0; jj < JT; jj++) {
        float v = acc[jj] + bias[j0 + jj];
        rr[jj] = v > 0.f ? v : 0.f;
    }
    float4* o = (float4*)(out + (size_t)tid * TV + j0);
    o[0] = make_float4(rr[0], rr[1], rr[2], rr[3]);
    o[1] = make_float4(rr[4], rr[5], rr[6], rr[7]);
}

extern "C" void kernel_launch(void* const* d_in, const int* in_sizes, int n_in,
                              void* d_out, int out_size) {
    const void*  x    = d_in[0];                 // [256, 16] int64/int32
    const float* W    = (const float*)d_in[1];   // [16384, 16384]
    const float* bias = (const float*)d_in[2];   // [16384]
    float* out = (float*)d_out;                  // [256, 16384]

    const int smem_bytes = NBUF * QBYTES;        // 64 KB dynamic -> 3 CTAs/SM
    static bool attr_set = false;
    if (!attr_set) {
        cudaFuncSetAttribute(gather_sum_relu_kernel,
                             cudaFuncAttributeMaxDynamicSharedMemorySize, smem_bytes);
        attr_set = true;
    }

    gather_sum_relu_kernel<<<TV / JT, NTHREADS, smem_bytes>>>(x, W, bias, out);
}